// round 3
// baseline (speedup 1.0000x reference)
#include <cuda_runtime.h>
#include <math.h>

#define Bsz  512
#define Tlen 512
#define Idim 128
#define Hdim 512
#define Odim 128
#define KTOT (Idim + Hdim)   /* 640 */
#define N4H  (4 * Hdim)      /* 2048 */

// Scratch (static device allocations are the sanctioned route; no cudaMalloc).
__device__ float g_Wr[KTOT * N4H];      // gate-interleaved [Wx;Wh]: col' = 4*j + gate
__device__ float g_br[N4H];             // gate-interleaved bias
__device__ float g_h[2][Bsz * Hdim];    // ping-pong hidden state
__device__ float g_c[Bsz * Hdim];       // cell state (pointwise-owned, single buffer)

// ---------------------------------------------------------------------------
// Reorder weights once per launch: Wr[k][4j+g] = (k<I ? Wx : Wh)[k'][g*H + j]
// ---------------------------------------------------------------------------
__global__ void prep_kernel(const float* __restrict__ Wx,
                            const float* __restrict__ Wh,
                            const float* __restrict__ b) {
    int idx = blockIdx.x * blockDim.x + threadIdx.x;
    const int total = KTOT * N4H;
    for (; idx < total; idx += gridDim.x * blockDim.x) {
        int k   = idx / N4H;
        int col = idx % N4H;
        int j = col >> 2;
        int g = col & 3;
        float v = (k < Idim) ? Wx[k * N4H + g * Hdim + j]
                             : Wh[(k - Idim) * N4H + g * Hdim + j];
        g_Wr[idx] = v;
        if (k == 0) g_br[col] = b[g * Hdim + j];
    }
}

__global__ void zero_kernel() {
    int idx = blockIdx.x * blockDim.x + threadIdx.x;
    if (idx < Bsz * Hdim) {
        g_h[0][idx] = 0.0f;
        g_c[idx]    = 0.0f;
    }
}

// ---------------------------------------------------------------------------
// One LSTM step, fully fused:
//   z[b, 4j+g] = [x_t | h_in][b, :] @ Wr[:, 4j+g] + br
//   cell update in epilogue, writes h_out and c.
// Tiling: BM=64 batch rows x BN=64 reordered cols (=16 hidden units x 4 gates),
// 256 threads, 4x4 micro-tile per thread (4 rows x one hidden unit's 4 gates).
// ---------------------------------------------------------------------------
#define BM 64
#define BN 64
#define BK 16

__global__ __launch_bounds__(256, 2)
void lstm_step(const float* __restrict__ x, int t, int parity) {
    __shared__ float As[2][BK][BM + 4];   // +4 pad keeps 16B alignment (68*4=272B)
    __shared__ float Bs[2][BK][BN];

    const float* __restrict__ h_in  = g_h[parity];
    float*       __restrict__ h_out = g_h[parity ^ 1];

    const int tid = threadIdx.x;
    const int tx  = tid & 15;          // hidden-unit group within tile (16)
    const int ty  = tid >> 4;          // row group (16)
    const int m0  = blockIdx.y * BM;   // batch-row base
    const int n0  = blockIdx.x * BN;   // reordered-col base (multiple of 64)

    // A-tile loader mapping: one float4 along k per thread
    const int lam = tid & 63;          // m within tile
    const int lak = (tid >> 6) << 2;   // k offset: 0,4,8,12
    // B-tile loader mapping: one float4 along n per thread
    const int lbn = (tid & 15) << 2;
    const int lbk = tid >> 4;

    float acc[4][4];
#pragma unroll
    for (int r = 0; r < 4; r++)
#pragma unroll
        for (int c = 0; c < 4; c++) acc[r][c] = g_br[n0 + 4 * tx + c];

    const float* aRowX = x + (size_t)(m0 + lam) * (Tlen * Idim) + (size_t)t * Idim;
    const float* aRowH = h_in + (m0 + lam) * Hdim;

    // Preload k-tile 0 (entirely inside the x segment since Idim=128 >= BK)
    {
        float4 av = *(const float4*)(aRowX + lak);
        float4 bv = *(const float4*)(g_Wr + (size_t)lbk * N4H + n0 + lbn);
        As[0][lak + 0][lam] = av.x;
        As[0][lak + 1][lam] = av.y;
        As[0][lak + 2][lam] = av.z;
        As[0][lak + 3][lam] = av.w;
        *(float4*)&Bs[0][lbk][lbn] = bv;
    }
    __syncthreads();

#pragma unroll 1
    for (int kt = 0; kt < KTOT; kt += BK) {
        const int buf  = (kt / BK) & 1;
        const bool more = (kt + BK) < KTOT;
        float4 an, bn_;
        if (more) {
            const int kn = kt + BK;            // tile never straddles Idim (128%16==0)
            const int ka = kn + lak;
            an  = (ka < Idim) ? *(const float4*)(aRowX + ka)
                              : *(const float4*)(aRowH + (ka - Idim));
            bn_ = *(const float4*)(g_Wr + (size_t)(kn + lbk) * N4H + n0 + lbn);
        }
#pragma unroll
        for (int kk = 0; kk < BK; kk++) {
            float4 a  = *(const float4*)&As[buf][kk][4 * ty];
            float4 bq = *(const float4*)&Bs[buf][kk][4 * tx];
            acc[0][0] += a.x * bq.x; acc[0][1] += a.x * bq.y;
            acc[0][2] += a.x * bq.z; acc[0][3] += a.x * bq.w;
            acc[1][0] += a.y * bq.x; acc[1][1] += a.y * bq.y;
            acc[1][2] += a.y * bq.z; acc[1][3] += a.y * bq.w;
            acc[2][0] += a.z * bq.x; acc[2][1] += a.z * bq.y;
            acc[2][2] += a.z * bq.z; acc[2][3] += a.z * bq.w;
            acc[3][0] += a.w * bq.x; acc[3][1] += a.w * bq.y;
            acc[3][2] += a.w * bq.z; acc[3][3] += a.w * bq.w;
        }
        if (more) {
            const int nb = buf ^ 1;
            As[nb][lak + 0][lam] = an.x;
            As[nb][lak + 1][lam] = an.y;
            As[nb][lak + 2][lam] = an.z;
            As[nb][lak + 3][lam] = an.w;
            *(float4*)&Bs[nb][lbk][lbn] = bn_;
        }
        __syncthreads();
    }

    // Fused LSTM cell epilogue: this thread owns hidden unit j for 4 batch rows.
    const int j = (n0 >> 2) + tx;
#pragma unroll
    for (int r = 0; r < 4; r++) {
        const int m   = m0 + 4 * ty + r;
        const int idx = m * Hdim + j;
        const float zg = acc[r][0];
        const float zi = acc[r][1];
        const float zf = acc[r][2];
        const float zo = acc[r][3];
        const float gg = tanhf(zg);
        const float ii = 1.0f / (1.0f + expf(-zi));
        const float ff = 1.0f / (1.0f + expf(-zf));
        const float oo = 1.0f / (1.0f + expf(-zo));
        const float cn = gg * ii + g_c[idx] * ff;
        g_c[idx]   = cn;
        h_out[idx] = tanhf(cn) * oo;
    }
}

// ---------------------------------------------------------------------------
// Final projection + row softmax: one CTA per batch row, one thread per output.
// ---------------------------------------------------------------------------
__global__ void proj_softmax(const float* __restrict__ Wp,
                             const float* __restrict__ bp,
                             float* __restrict__ out) {
    __shared__ float hrow[Hdim];
    __shared__ float red[Odim];
    const int b = blockIdx.x;
    const int o = threadIdx.x;

    const float* h = g_h[0] + b * Hdim;   // T=512 even -> final state lands in g_h[0]
    for (int k = o; k < Hdim; k += Odim) hrow[k] = h[k];
    __syncthreads();

    float acc = bp[o];
#pragma unroll 8
    for (int k = 0; k < Hdim; k++) acc += hrow[k] * Wp[k * Odim + o];

    red[o] = acc;
    __syncthreads();
    for (int s = Odim / 2; s > 0; s >>= 1) {
        if (o < s) red[o] = fmaxf(red[o], red[o + s]);
        __syncthreads();
    }
    const float mx = red[0];
    __syncthreads();
    const float e = expf(acc - mx);
    red[o] = e;
    __syncthreads();
    for (int s = Odim / 2; s > 0; s >>= 1) {
        if (o < s) red[o] += red[o + s];
        __syncthreads();
    }
    out[b * Odim + o] = e / red[0];
}

// ---------------------------------------------------------------------------
extern "C" void kernel_launch(void* const* d_in, const int* in_sizes, int n_in,
                              void* d_out, int out_size) {
    const float* x  = (const float*)d_in[0];
    const float* Wx = (const float*)d_in[1];
    const float* Wh = (const float*)d_in[2];
    const float* b  = (const float*)d_in[3];
    const float* Wp = (const float*)d_in[4];
    const float* bp = (const float*)d_in[5];
    float* out = (float*)d_out;

    prep_kernel<<<512, 256>>>(Wx, Wh, b);
    zero_kernel<<<(Bsz * Hdim + 255) / 256, 256>>>();

    dim3 grid(N4H / BN, Bsz / BM);   // (32, 8) = 256 CTAs
    for (int t = 0; t < Tlen; t++) {
        lstm_step<<<grid, 256>>>(x, t, t & 1);
    }
    proj_softmax<<<Bsz, Odim>>>(Wp, bp, out);
}

// round 6
// speedup vs baseline: 1.9874x; 1.9874x over previous
#include <cuda_runtime.h>
#include <cuda_bf16.h>
#include <stdint.h>
#include <math.h>

#define Bsz  512
#define Tlen 512
#define Idim 128
#define Hdim 512
#define Odim 128
#define KTOT 640
#define N4H  2048
#define NCH  20              /* k-chunks of 32 */

// ---------------- static device scratch ------------------------------------
// Weights pre-split to bf16 hi/lo, gate-interleaved, grouped per (n-tile, chunk)
// as contiguous [64 n][32 k] blocks: off = ((ni*NCH + c)*2048 + n*32 + k).
__device__ unsigned short g_Bhi[(size_t)KTOT * N4H];
__device__ unsigned short g_Blo[(size_t)KTOT * N4H];
__device__ float g_br[N4H];            // gate-interleaved bias: col = 4*j + gate
__device__ float g_h[2][Bsz * Hdim];   // ping-pong hidden state (fp32)
__device__ float g_c[Bsz * Hdim];      // cell state

// ---------------- helpers ---------------------------------------------------
__device__ __forceinline__ uint32_t smem_u32(const void* p) {
    uint32_t a;
    asm("{ .reg .u64 t; cvta.to.shared.u64 t, %1; cvt.u32.u64 %0, t; }" : "=r"(a) : "l"(p));
    return a;
}
__device__ __forceinline__ void bf16_split(float f, unsigned short& hi, unsigned short& lo) {
    __nv_bfloat16 h = __float2bfloat16(f);
    __nv_bfloat16 l = __float2bfloat16(f - __bfloat162float(h));
    hi = __bfloat16_as_ushort(h);
    lo = __bfloat16_as_ushort(l);
}
__device__ __forceinline__ void ldm4(uint32_t* r, uint32_t addr) {
    asm("ldmatrix.sync.aligned.m8n8.x4.shared.b16 {%0,%1,%2,%3}, [%4];"
        : "=r"(r[0]), "=r"(r[1]), "=r"(r[2]), "=r"(r[3]) : "r"(addr));
}
__device__ __forceinline__ void mma_bf16(float* d, const uint32_t* a, uint32_t b0, uint32_t b1) {
    asm("mma.sync.aligned.m16n8k16.row.col.f32.bf16.bf16.f32 "
        "{%0,%1,%2,%3}, {%4,%5,%6,%7}, {%8,%9}, {%0,%1,%2,%3};"
        : "+f"(d[0]), "+f"(d[1]), "+f"(d[2]), "+f"(d[3])
        : "r"(a[0]), "r"(a[1]), "r"(a[2]), "r"(a[3]), "r"(b0), "r"(b1));
}
__device__ __forceinline__ float sigf(float z) { return 1.0f / (1.0f + expf(-z)); }

// ---------------------------------------------------------------------------
// prep: gate-interleave + bf16 hi/lo split of [Wx;Wh] into per-(ni,chunk)
// contiguous blocks. item = (k, j); handles all 4 gates of (k, j).
// ---------------------------------------------------------------------------
__global__ void prep_kernel(const float* __restrict__ Wx,
                            const float* __restrict__ Wh,
                            const float* __restrict__ b) {
    int item = blockIdx.x * blockDim.x + threadIdx.x;
    if (item >= KTOT * Hdim) return;
    const int k = item >> 9;          // 0..639
    const int j = item & 511;
#pragma unroll
    for (int g = 0; g < 4; g++) {
        const float w = (k < Idim) ? Wx[k * N4H + g * Hdim + j]
                                   : Wh[(k - Idim) * N4H + g * Hdim + j];
        unsigned short hi, lo;
        bf16_split(w, hi, lo);
        const int n  = 4 * j + g;
        const int ni = n >> 6, nl = n & 63;
        const int c  = k >> 5, kk = k & 31;
        const size_t off = ((size_t)(ni * NCH + c)) * 2048 + nl * 32 + kk;
        g_Bhi[off] = hi;
        g_Blo[off] = lo;
        if (k == 0) g_br[n] = b[g * Hdim + j];
    }
}

__global__ void zero_kernel() {
    int idx = blockIdx.x * blockDim.x + threadIdx.x;
    if (idx < Bsz * Hdim) { g_h[0][idx] = 0.0f; g_c[idx] = 0.0f; }
}

// ---------------------------------------------------------------------------
// One LSTM step on warp-level bf16 MMA (HMMA). CTA: 128 m x 64 n, K=640 in
// 20 chunks of 32, register-prefetched, 3-term bf16-split. Fused LSTM epilogue.
// smem rows padded to 80B for conflict-free ldmatrix.
// ---------------------------------------------------------------------------
#define OFF_A    0                        /* [split][buf] 128x80B = 10240 each */
#define OFF_B    40960                    /* [split][buf]  64x80B =  5120 each */
#define OFF_BIAS 61440                    /* 64 floats */
#define OFF_SC   61696                    /* c stage: 128 x 20 floats */
#define OFF_SH   71936                    /* h stage: 128 x 20 floats */
#define SMEM_BYTES 82176

__global__ __launch_bounds__(256)
void lstm_step(const float* __restrict__ x, int t, int parity) {
    extern __shared__ __align__(16) char smem[];
    const uint32_t sb = smem_u32(smem);
    const int tid  = threadIdx.x;
    const int wid  = tid >> 5;
    const int lane = tid & 31;
    const int ni = blockIdx.x;            // 0..31
    const int m0 = blockIdx.y * 128;      // 0..3 -> row base
    const int warp_m = (wid & 3) * 32;
    const int warp_n = (wid >> 2) * 32;
    const float* __restrict__ h_in  = g_h[parity];
    float*       __restrict__ h_out = g_h[parity ^ 1];

    // bias + cell-state stage-in (coalesced)
    if (tid < 64) ((float*)(smem + OFF_BIAS))[tid] = g_br[ni * 64 + tid];
    {
        const int row = tid >> 1, q2 = (tid & 1) * 2;
        const float* csrc = g_c + (size_t)(m0 + row) * Hdim + ni * 16;
        float* sc = (float*)(smem + OFF_SC) + row * 20;
        *(float4*)(sc + q2 * 4)     = *(const float4*)(csrc + q2 * 4);
        *(float4*)(sc + q2 * 4 + 4) = *(const float4*)(csrc + q2 * 4 + 4);
    }

    // prefetch mappings
    const int row_a = tid >> 1;           // A row this thread loads (0..127)
    const int ka0   = (tid & 1) * 16;     // k offset of its 16 floats
    const float* xbase = x + (size_t)(m0 + row_a) * (Tlen * Idim) + (size_t)t * Idim + ka0;
    const float* hbase = h_in + (size_t)(m0 + row_a) * Hdim + ka0;

    float4 af[4];
    uint4  bfh, bfl;
#define LOAD_CHUNK(c)  do {                                                      \
        const float* s_ = ((c) < 4) ? (xbase + (c) * 32) : (hbase + ((c)-4) * 32);\
        af[0] = *(const float4*)(s_);      af[1] = *(const float4*)(s_ + 4);      \
        af[2] = *(const float4*)(s_ + 8);  af[3] = *(const float4*)(s_ + 12);     \
        const size_t bo_ = ((size_t)(ni * NCH + (c))) * 2048 + tid * 8;           \
        bfh = *(const uint4*)(g_Bhi + bo_);                                       \
        bfl = *(const uint4*)(g_Blo + bo_);                                       \
    } while (0)

    float acc[2][4][4];
#pragma unroll
    for (int a1 = 0; a1 < 2; a1++)
#pragma unroll
        for (int a2 = 0; a2 < 4; a2++)
#pragma unroll
            for (int a3 = 0; a3 < 4; a3++) acc[a1][a2][a3] = 0.0f;

    LOAD_CHUNK(0);

#pragma unroll 1
    for (int c = 0; c < NCH; c++) {
        const int buf = c & 1;
        // ---- store prefetched chunk into smem (bf16 split for A) ----
        {
            uint32_t* aH = (uint32_t*)(smem + OFF_A + buf * 10240) + row_a * 20 + (tid & 1) * 8;
            uint32_t* aL = (uint32_t*)((char*)aH + 20480);
#pragma unroll
            for (int i = 0; i < 4; i++) {
                unsigned short h0, l0, h1, l1, h2, l2, h3, l3;
                bf16_split(af[i].x, h0, l0); bf16_split(af[i].y, h1, l1);
                bf16_split(af[i].z, h2, l2); bf16_split(af[i].w, h3, l3);
                *(uint2*)(aH + i * 2) = make_uint2((uint32_t)h0 | ((uint32_t)h1 << 16),
                                                   (uint32_t)h2 | ((uint32_t)h3 << 16));
                *(uint2*)(aL + i * 2) = make_uint2((uint32_t)l0 | ((uint32_t)l1 << 16),
                                                   (uint32_t)l2 | ((uint32_t)l3 << 16));
            }
            char* bH = smem + OFF_B + buf * 5120 + (tid >> 2) * 80 + (tid & 3) * 16;
            *(uint4*)bH            = bfh;
            *(uint4*)(bH + 10240)  = bfl;
        }
        __syncthreads();
        if (c + 1 < NCH) LOAD_CHUNK(c + 1);

        // ---- compute chunk: 2 k16-steps, 24 MMA each ----
        const uint32_t baseAh = sb + OFF_A + buf * 10240
                              + (warp_m + (lane & 15)) * 80 + (lane >> 4) * 16;
        const uint32_t baseBh = sb + OFF_B + buf * 5120
                              + (warp_n + (lane & 15)) * 80 + (lane >> 4) * 16;
#pragma unroll
        for (int ks = 0; ks < 2; ks++) {
            uint32_t ah[2][4], al[2][4], bh[2][4], bl[2][4];
            ldm4(ah[0], baseAh + ks * 32);
            ldm4(ah[1], baseAh + 16 * 80 + ks * 32);
            ldm4(al[0], baseAh + 20480 + ks * 32);
            ldm4(al[1], baseAh + 20480 + 16 * 80 + ks * 32);
            ldm4(bh[0], baseBh + ks * 32);
            ldm4(bh[1], baseBh + 16 * 80 + ks * 32);
            ldm4(bl[0], baseBh + 10240 + ks * 32);
            ldm4(bl[1], baseBh + 10240 + 16 * 80 + ks * 32);
#pragma unroll
            for (int mb = 0; mb < 2; mb++) {
#pragma unroll
                for (int nh = 0; nh < 2; nh++) {
                    mma_bf16(acc[mb][nh * 2 + 0], ah[mb], bh[nh][0], bh[nh][2]);
                    mma_bf16(acc[mb][nh * 2 + 1], ah[mb], bh[nh][1], bh[nh][3]);
                    mma_bf16(acc[mb][nh * 2 + 0], ah[mb], bl[nh][0], bl[nh][2]);
                    mma_bf16(acc[mb][nh * 2 + 1], ah[mb], bl[nh][1], bl[nh][3]);
                    mma_bf16(acc[mb][nh * 2 + 0], al[mb], bh[nh][0], bh[nh][2]);
                    mma_bf16(acc[mb][nh * 2 + 1], al[mb], bh[nh][1], bh[nh][3]);
                }
            }
        }
        __syncthreads();
    }

    // ---- fused LSTM cell epilogue ----
    {
        float* sbias = (float*)(smem + OFF_BIAS);
        float* sc    = (float*)(smem + OFF_SC);
        float* sh    = (float*)(smem + OFF_SH);
        const int lq = lane & 3, lr = lane >> 2, odd = lane & 1;
#pragma unroll
        for (int mb = 0; mb < 2; mb++) {
#pragma unroll
            for (int nb = 0; nb < 4; nb++) {
                float* a = acc[mb][nb];
                const float t0 = __shfl_xor_sync(0xffffffffu, a[0], 1);
                const float t1 = __shfl_xor_sync(0xffffffffu, a[1], 1);
                const float t2 = __shfl_xor_sync(0xffffffffu, a[2], 1);
                const float t3 = __shfl_xor_sync(0xffffffffu, a[3], 1);
                float zg, zi, zf, zo;
                if (!odd) { zg = a[0]; zi = a[1]; zf = t0;   zo = t1;   }
                else      { zg = t2;   zi = t3;   zf = a[2]; zo = a[3]; }
                const int r   = warp_m + mb * 16 + lr + odd * 8;
                const int jl  = (warp_n >> 2) + nb * 2 + (lq >> 1);
                const int nb4 = warp_n + nb * 8 + (lq >> 1) * 4;
                zg += sbias[nb4 + 0]; zi += sbias[nb4 + 1];
                zf += sbias[nb4 + 2]; zo += sbias[nb4 + 3];
                const float gg = tanhf(zg);
                const float ii = sigf(zi);
                const float ff = sigf(zf);
                const float oo = sigf(zo);
                const float cn = gg * ii + sc[r * 20 + jl] * ff;
                sc[r * 20 + jl] = cn;
                sh[r * 20 + jl] = tanhf(cn) * oo;
            }
        }
    }
    __syncthreads();
    // coalesced stage-out of h and c
    {
        const int row = tid >> 1, q2 = (tid & 1) * 2;
        float* sh = (float*)(smem + OFF_SH) + row * 20;
        float* sc = (float*)(smem + OFF_SC) + row * 20;
        float* hd = h_out + (size_t)(m0 + row) * Hdim + ni * 16;
        float* cd = g_c   + (size_t)(m0 + row) * Hdim + ni * 16;
        *(float4*)(hd + q2 * 4)     = *(float4*)(sh + q2 * 4);
        *(float4*)(hd + q2 * 4 + 4) = *(float4*)(sh + q2 * 4 + 4);
        *(float4*)(cd + q2 * 4)     = *(float4*)(sc + q2 * 4);
        *(float4*)(cd + q2 * 4 + 4) = *(float4*)(sc + q2 * 4 + 4);
    }
}

// ---------------------------------------------------------------------------
// Final projection + row softmax.
// ---------------------------------------------------------------------------
__global__ void proj_softmax(const float* __restrict__ Wp,
                             const float* __restrict__ bp,
                             float* __restrict__ out) {
    __shared__ float hrow[Hdim];
    __shared__ float red[Odim];
    const int b = blockIdx.x;
    const int o = threadIdx.x;

    const float* h = g_h[0] + b * Hdim;   // T=512 even -> final state in g_h[0]
    for (int k = o; k < Hdim; k += Odim) hrow[k] = h[k];
    __syncthreads();

    float acc = bp[o];
#pragma unroll 8
    for (int k = 0; k < Hdim; k++) acc += hrow[k] * Wp[k * Odim + o];

    red[o] = acc;
    __syncthreads();
    for (int s = Odim / 2; s > 0; s >>= 1) {
        if (o < s) red[o] = fmaxf(red[o], red[o + s]);
        __syncthreads();
    }
    const float mx = red[0];
    __syncthreads();
    const float e = expf(acc - mx);
    red[o] = e;
    __syncthreads();
    for (int s = Odim / 2; s > 0; s >>= 1) {
        if (o < s) red[o] += red[o + s];
        __syncthreads();
    }
    out[b * Odim + o] = e / red[0];
}

// ---------------------------------------------------------------------------
extern "C" void kernel_launch(void* const* d_in, const int* in_sizes, int n_in,
                              void* d_out, int out_size) {
    const float* x  = (const float*)d_in[0];
    const float* Wx = (const float*)d_in[1];
    const float* Wh = (const float*)d_in[2];
    const float* b  = (const float*)d_in[3];
    const float* Wp = (const float*)d_in[4];
    const float* bp = (const float*)d_in[5];
    float* out = (float*)d_out;

    cudaFuncSetAttribute(lstm_step, cudaFuncAttributeMaxDynamicSharedMemorySize, SMEM_BYTES);

    prep_kernel<<<(KTOT * Hdim + 255) / 256, 256>>>(Wx, Wh, b);
    zero_kernel<<<(Bsz * Hdim + 255) / 256, 256>>>();

    dim3 grid(N4H / 64, Bsz / 128);      // (32, 4) = 128 CTAs
    for (int t = 0; t < Tlen; t++) {
        lstm_step<<<grid, 256, SMEM_BYTES>>>(x, t, t & 1);
    }
    proj_softmax<<<Bsz, Odim>>>(Wp, bp, out);
}